// round 16
// baseline (speedup 1.0000x reference)
#include <cuda_runtime.h>
#include <cuda_fp16.h>
#include <math.h>
#include <stdint.h>

// ---------------- Problem constants ----------------
#define DIM   128
#define E_MAX 100000
#define P_MAX 800000
#define G_MAX 1000
#define TSTEPS 8

// ---------------- Device scratch (no allocations allowed) ----------------
__device__ float d_h  [E_MAX * DIM];
__device__ float d_agg[E_MAX * DIM];
__device__ float d_UV [E_MAX * 256];
__device__ float d_S  [E_MAX * 256];   // z,r pre-activation sums
__device__ float d_X1h[E_MAX * 128];   // agg @ Wk_h + b0h
__device__ float d_X2h[E_MAX * 128];   // h   @ Wrk_h + b1h
__device__ float d_pool[G_MAX * DIM];
__device__ float d_r1 [G_MAX * 256];
__device__ float d_r2 [G_MAX * 256];
__device__ float d_b256[256];          // [0..127]=0, [128..255]=b_msg
__device__ float d_bzr[256];           // gru_b[0][0:256] + gru_b[1][0:256]
// split+transposed weights, rows:
//   0..255   Wk_zr^T   (gru_k cols 0..255)
//   256..511 Wrk_zr^T  (gru_rk cols 0..255)
//   512..639 Wk_h^T    (gru_k cols 256..383)
//   640..767 Wrk_h^T   (gru_rk cols 256..383)
//   768..1023 Wuv^T
__device__ __half d_WtHi[1024 * 128];
__device__ __half d_WtLo[1024 * 128];
// CSR grouping of pairs by `second`
__device__ int d_off   [E_MAX + 1];
__device__ int d_cur   [E_MAX];
__device__ int d_pfirst[P_MAX];
__device__ int d_blk   [256];

// ---------------- math helpers ----------------
__device__ __forceinline__ float selu_f(float x) {
    const float sc = 1.0507009873554805f;
    const float al = 1.6732632423543772f;
    return x > 0.f ? sc * x : sc * al * (expf(x) - 1.f);
}
__device__ __forceinline__ float sigmoid_f(float x) { return 1.f / (1.f + expf(-x)); }

__device__ __forceinline__ uint32_t smem_u32(const void* p) {
    uint32_t a;
    asm("{ .reg .u64 t; cvta.to.shared.u64 t, %1; cvt.u32.u64 %0, t; }" : "=r"(a) : "l"(p));
    return a;
}

#define CP_ASYNC16(dst, src) \
    asm volatile("cp.async.cg.shared.global [%0], [%1], 16;" :: "r"(dst), "l"(src))
#define CP_COMMIT() asm volatile("cp.async.commit_group;" ::: "memory")
#define CP_WAIT0()  asm volatile("cp.async.wait_group 0;" ::: "memory")

// swizzled byte offset of 16B chunk c8 (0..15) in row r (256B rows)
__device__ __forceinline__ uint32_t sw_off(int r, int c8) {
    return ((uint32_t)r << 8) + (uint32_t)((c8 ^ (r & 7)) << 4);
}

__device__ __forceinline__ void ldsm_x4(uint32_t addr, uint32_t* r) {
    asm volatile("ldmatrix.sync.aligned.m8n8.x4.shared.b16 {%0,%1,%2,%3}, [%4];"
                 : "=r"(r[0]), "=r"(r[1]), "=r"(r[2]), "=r"(r[3]) : "r"(addr));
}

__device__ __forceinline__ void mma16816(float* c, const uint32_t* a, uint32_t b0, uint32_t b1) {
    asm volatile(
        "mma.sync.aligned.m16n8k16.row.col.f32.f16.f16.f32 "
        "{%0,%1,%2,%3}, {%4,%5,%6,%7}, {%8,%9}, {%0,%1,%2,%3};"
        : "+f"(c[0]), "+f"(c[1]), "+f"(c[2]), "+f"(c[3])
        : "r"(a[0]), "r"(a[1]), "r"(a[2]), "r"(a[3]), "r"(b0), "r"(b1));
}

// split fp32 float4 into fp16 hi/lo pairs packed as uint2
__device__ __forceinline__ void split4(float4 v, uint2& hu, uint2& lu) {
    __half2 h01 = __floats2half2_rn(v.x, v.y);
    __half2 h23 = __floats2half2_rn(v.z, v.w);
    float lx = v.x - __half2float(__low2half(h01));
    float ly = v.y - __half2float(__high2half(h01));
    float lz = v.z - __half2float(__low2half(h23));
    float lw = v.w - __half2float(__high2half(h23));
    __half2 l01 = __floats2half2_rn(lx, ly);
    __half2 l23 = __floats2half2_rn(lz, lw);
    hu.x = *(uint32_t*)&h01; hu.y = *(uint32_t*)&h23;
    lu.x = *(uint32_t*)&l01; lu.y = *(uint32_t*)&l23;
}

// ---------------- Weight prep ----------------
__global__ void prep_weights(const float* __restrict__ gru_k, const float* __restrict__ gru_rk,
                             const float* __restrict__ W_msg, const float* __restrict__ b_msg,
                             const float* __restrict__ gru_b,
                             __half* __restrict__ WtHi, __half* __restrict__ WtLo,
                             float* __restrict__ b256, float* __restrict__ bzr)
{
    int i = blockIdx.x * blockDim.x + threadIdx.x;
    if (i >= 1024 * 128) return;
    if (i < 256) bzr[i] = gru_b[i] + gru_b[384 + i];
    else if (i < 512) { int j = i - 256; b256[j] = (j < 128) ? 0.f : b_msg[j - 128]; }
    int n = i >> 7;
    int k = i & 127;
    float v;
    if (n < 256) {
        v = gru_k[k * 384 + n];
    } else if (n < 512) {
        v = gru_rk[k * 384 + (n - 256)];
    } else if (n < 640) {
        v = gru_k[k * 384 + 256 + (n - 512)];
    } else if (n < 768) {
        v = gru_rk[k * 384 + 256 + (n - 640)];
    } else {
        int j = n - 768;
        v = (j < 128) ? W_msg[k * 128 + j] : W_msg[(128 + k) * 128 + (j - 128)];
    }
    __half hi = __float2half_rn(v);
    float lo = v - __half2float(hi);
    WtHi[i] = hi;
    WtLo[i] = __float2half_rn(lo);
}

// ================= CSR build: group pairs by `second` =================
__global__ void k_hist(const int* __restrict__ second, int* __restrict__ cnt, int P) {
    int p = blockIdx.x * blockDim.x + threadIdx.x;
    if (p < P) atomicAdd(&cnt[second[p] + 1], 1);
}

__global__ void k_scan1(int* __restrict__ data, int* __restrict__ blk, int n) {
    __shared__ int sh[1024];
    int tid = threadIdx.x;
    int i = blockIdx.x * 1024 + tid;
    int v = (i < n) ? data[i] : 0;
    sh[tid] = v;
    __syncthreads();
    #pragma unroll
    for (int off = 1; off < 1024; off <<= 1) {
        int t = (tid >= off) ? sh[tid - off] : 0;
        __syncthreads();
        sh[tid] += t;
        __syncthreads();
    }
    if (i < n) data[i] = sh[tid];
    if (tid == 1023) blk[blockIdx.x] = sh[1023];
}

__global__ void k_scan2(int* __restrict__ blk, int nb) {
    __shared__ int sh[1024];
    int tid = threadIdx.x;
    int v = (tid < nb) ? blk[tid] : 0;
    sh[tid] = v;
    __syncthreads();
    #pragma unroll
    for (int off = 1; off < 1024; off <<= 1) {
        int t = (tid >= off) ? sh[tid - off] : 0;
        __syncthreads();
        sh[tid] += t;
        __syncthreads();
    }
    if (tid < nb) blk[tid] = sh[tid] - v;   // exclusive
}

__global__ void k_scan3(int* __restrict__ data, const int* __restrict__ blk,
                        int* __restrict__ cur, int n, int E) {
    int i = blockIdx.x * 1024 + threadIdx.x;
    if (i >= n) return;
    int v = data[i] + blk[blockIdx.x];
    data[i] = v;
    if (i < E) cur[i] = v;
}

__global__ void k_scatter(const int* __restrict__ first, const int* __restrict__ second,
                          int* __restrict__ cur, int* __restrict__ pfirst, int P) {
    int p = blockIdx.x * blockDim.x + threadIdx.x;
    if (p >= P) return;
    int s = second[p];
    int idx = atomicAdd(&cur[s], 1);
    pfirst[idx] = first[p];
}

// ================= Segment message sum =================
__global__ void seg_msg(const float* __restrict__ UV,
                        const int* __restrict__ off, const int* __restrict__ pfirst,
                        float* __restrict__ agg, int E)
{
    int s = blockIdx.x * 8 + (threadIdx.x >> 5);
    if (s >= E) return;
    int lane = threadIdx.x & 31;
    int beg = off[s], end = off[s + 1];
    float4 vb = *(const float4*)(UV + (size_t)s * 256 + 128 + lane * 4);
    float4 acc = make_float4(0.f, 0.f, 0.f, 0.f);
    int i = beg;
    for (; i + 4 <= end; i += 4) {
        int f0 = pfirst[i];
        int f1 = pfirst[i + 1];
        int f2 = pfirst[i + 2];
        int f3 = pfirst[i + 3];
        float4 u0 = *(const float4*)(UV + (size_t)f0 * 256 + lane * 4);
        float4 u1 = *(const float4*)(UV + (size_t)f1 * 256 + lane * 4);
        float4 u2 = *(const float4*)(UV + (size_t)f2 * 256 + lane * 4);
        float4 u3 = *(const float4*)(UV + (size_t)f3 * 256 + lane * 4);
        acc.x += selu_f(u0.x + vb.x) + selu_f(u1.x + vb.x) + selu_f(u2.x + vb.x) + selu_f(u3.x + vb.x);
        acc.y += selu_f(u0.y + vb.y) + selu_f(u1.y + vb.y) + selu_f(u2.y + vb.y) + selu_f(u3.y + vb.y);
        acc.z += selu_f(u0.z + vb.z) + selu_f(u1.z + vb.z) + selu_f(u2.z + vb.z) + selu_f(u3.z + vb.z);
        acc.w += selu_f(u0.w + vb.w) + selu_f(u1.w + vb.w) + selu_f(u2.w + vb.w) + selu_f(u3.w + vb.w);
    }
    for (; i < end; i++) {
        int f = pfirst[i];
        float4 u = *(const float4*)(UV + (size_t)f * 256 + lane * 4);
        acc.x += selu_f(u.x + vb.x);
        acc.y += selu_f(u.y + vb.y);
        acc.z += selu_f(u.z + vb.z);
        acc.w += selu_f(u.w + vb.w);
    }
    *(float4*)(agg + (size_t)s * 128 + lane * 4) = acc;
}

// ================= Tensor-core GEMM core (shared by both kernels) =================
#define SA_HI 0
#define SA_LO 24576
#define SB_HI 49152
#define SB_LO 81920
#define SMEM_SZ 114688

struct WarpCtx {
    uint32_t aBase[3], aX[3], bBase[2], bX[2], aC8, bC8;
    int wr, wc, lane;
};

__device__ __forceinline__ void init_ctx(WarpCtx& cx, int tid) {
    int wid = tid >> 5;
    cx.lane = tid & 31;
    cx.wr = wid >> 2;
    cx.wc = wid & 3;
    int g = cx.lane >> 3;
    int l8 = cx.lane & 7;
    #pragma unroll
    for (int mt = 0; mt < 3; mt++) {
        int r = cx.wr * 48 + mt * 16 + (g & 1) * 8 + l8;
        cx.aBase[mt] = (uint32_t)r << 8;
        cx.aX[mt] = (uint32_t)(r & 7);
    }
    #pragma unroll
    for (int nt = 0; nt < 2; nt++) {
        int r = cx.wc * 32 + nt * 16 + (g >> 1) * 8 + l8;
        cx.bBase[nt] = (uint32_t)r << 8;
        cx.bX[nt] = (uint32_t)(r & 7);
    }
    cx.aC8 = (uint32_t)(g >> 1);
    cx.bC8 = (uint32_t)(g & 1);
}

// load B tile (cp.async), load+split A tile, sync
__device__ __forceinline__ void load_tiles(char* smem, uint32_t sb, int tid,
                                           const float* A, int row0, int M,
                                           const __half* BH, const __half* BL) {
    #pragma unroll
    for (int it = 0; it < 16; it++) {
        int idx = it * 256 + tid;
        int m = idx >> 11;
        int ci = idx & 2047;
        int n = ci >> 4;
        int c8 = ci & 15;
        const __half* src = (m ? BL : BH) + (size_t)n * 128 + c8 * 8;
        uint32_t dst = sb + (m ? SB_LO : SB_HI) + sw_off(n, c8);
        CP_ASYNC16(dst, src);
    }
    CP_COMMIT();
    #pragma unroll
    for (int it = 0; it < 12; it++) {
        int idx = it * 256 + tid;
        int r = idx >> 5;
        int c4 = idx & 31;
        int grow = row0 + r;
        float4 v = make_float4(0.f, 0.f, 0.f, 0.f);
        if (grow < M) v = *(const float4*)(A + (size_t)grow * 128 + c4 * 4);
        uint2 hu, lu;
        split4(v, hu, lu);
        uint32_t off = ((uint32_t)r << 8) + (uint32_t)((((c4 >> 1) ^ (r & 7)) << 4) | ((c4 & 1) << 3));
        *(uint2*)(smem + SA_HI + off) = hu;
        *(uint2*)(smem + SA_LO + off) = lu;
    }
    CP_WAIT0();
    __syncthreads();
}

__device__ __forceinline__ void mainloop(uint32_t sb, const WarpCtx& cx, float acc[3][4][4]) {
    #pragma unroll
    for (int ks = 0; ks < 8; ks++) {
        uint32_t aHi[3][4], aLo[3][4];
        #pragma unroll
        for (int mt = 0; mt < 3; mt++) {
            uint32_t aoff = cx.aBase[mt] + ((((uint32_t)(2 * ks) + cx.aC8) ^ cx.aX[mt]) << 4);
            ldsm_x4(sb + SA_HI + aoff, aHi[mt]);
            ldsm_x4(sb + SA_LO + aoff, aLo[mt]);
        }
        uint32_t bHi[2][4], bLo[2][4];
        #pragma unroll
        for (int nt = 0; nt < 2; nt++) {
            uint32_t boff = cx.bBase[nt] + ((((uint32_t)(2 * ks) + cx.bC8) ^ cx.bX[nt]) << 4);
            ldsm_x4(sb + SB_HI + boff, bHi[nt]);
            ldsm_x4(sb + SB_LO + boff, bLo[nt]);
        }
        #pragma unroll
        for (int mt = 0; mt < 3; mt++)
            #pragma unroll
            for (int j = 0; j < 4; j++) {
                uint32_t b0 = (j & 1) ? bHi[j >> 1][2] : bHi[j >> 1][0];
                uint32_t b1 = (j & 1) ? bHi[j >> 1][3] : bHi[j >> 1][1];
                mma16816(acc[mt][j], aHi[mt], b0, b1);
            }
        #pragma unroll
        for (int mt = 0; mt < 3; mt++)
            #pragma unroll
            for (int j = 0; j < 4; j++) {
                uint32_t b0 = (j & 1) ? bLo[j >> 1][2] : bLo[j >> 1][0];
                uint32_t b1 = (j & 1) ? bLo[j >> 1][3] : bLo[j >> 1][1];
                mma16816(acc[mt][j], aHi[mt], b0, b1);
            }
        #pragma unroll
        for (int mt = 0; mt < 3; mt++)
            #pragma unroll
            for (int j = 0; j < 4; j++) {
                uint32_t b0 = (j & 1) ? bHi[j >> 1][2] : bHi[j >> 1][0];
                uint32_t b1 = (j & 1) ? bHi[j >> 1][3] : bHi[j >> 1][1];
                mma16816(acc[mt][j], aLo[mt], b0, b1);
            }
    }
}

__device__ __forceinline__ void epilogue(const WarpCtx& cx, float acc[3][4][4],
                                         const float* bias, float* C,
                                         int row0, int col0, int M, int Ntot) {
    #pragma unroll
    for (int mt = 0; mt < 3; mt++) {
        int r0a = row0 + cx.wr * 48 + mt * 16 + (cx.lane >> 2);
        #pragma unroll
        for (int j = 0; j < 4; j++) {
            int c = col0 + cx.wc * 32 + j * 8 + (cx.lane & 3) * 2;
            float b0 = bias ? bias[c] : 0.f;
            float b1 = bias ? bias[c + 1] : 0.f;
            if (r0a < M) {
                float2 v; v.x = acc[mt][j][0] + b0; v.y = acc[mt][j][1] + b1;
                *(float2*)(C + (size_t)r0a * Ntot + c) = v;
            }
            if (r0a + 8 < M) {
                float2 v; v.x = acc[mt][j][2] + b0; v.y = acc[mt][j][3] + b1;
                *(float2*)(C + (size_t)(r0a + 8) * Ntot + c) = v;
            }
        }
    }
}

// single-A GEMM: C[M, Ntot] = A @ Bt^T + bias, Bt rows at (bRow0 + col0 + n)
__global__ void __launch_bounds__(256, 2) mma_gemm(
    const float* __restrict__ A, const __half* __restrict__ BtHi,
    const __half* __restrict__ BtLo, const float* __restrict__ bias,
    float* __restrict__ C, int M, int Ntot, int bRow0)
{
    extern __shared__ __align__(128) char smem[];
    const uint32_t sb = smem_u32(smem);
    const int tid = threadIdx.x;
    const int row0 = blockIdx.x * 96;
    const int col0 = blockIdx.y * 128;

    float acc[3][4][4];
    #pragma unroll
    for (int i = 0; i < 3; i++)
        #pragma unroll
        for (int j = 0; j < 4; j++)
            #pragma unroll
            for (int q = 0; q < 4; q++) acc[i][j][q] = 0.f;

    WarpCtx cx;
    init_ctx(cx, tid);
    load_tiles(smem, sb, tid, A, row0, M,
               BtHi + (size_t)(bRow0 + col0) * 128, BtLo + (size_t)(bRow0 + col0) * 128);
    mainloop(sb, cx, acc);
    epilogue(cx, acc, bias, C, row0, col0, M, Ntot);
}

// two-phase K=256 GEMM: C = A1 @ B1^T + A2 @ B2^T + bias
// B1 rows at (col0+n), B2 rows at (256 + col0 + n). Ntot = 256.
__global__ void __launch_bounds__(256, 2) mma_gemm_zr(
    const float* __restrict__ A1, const float* __restrict__ A2,
    const __half* __restrict__ BtHi, const __half* __restrict__ BtLo,
    const float* __restrict__ bias, float* __restrict__ C, int M)
{
    extern __shared__ __align__(128) char smem[];
    const uint32_t sb = smem_u32(smem);
    const int tid = threadIdx.x;
    const int row0 = blockIdx.x * 96;
    const int col0 = blockIdx.y * 128;

    float acc[3][4][4];
    #pragma unroll
    for (int i = 0; i < 3; i++)
        #pragma unroll
        for (int j = 0; j < 4; j++)
            #pragma unroll
            for (int q = 0; q < 4; q++) acc[i][j][q] = 0.f;

    WarpCtx cx;
    init_ctx(cx, tid);

    // phase 1: agg @ Wk_zr
    load_tiles(smem, sb, tid, A1, row0, M,
               BtHi + (size_t)col0 * 128, BtLo + (size_t)col0 * 128);
    mainloop(sb, cx, acc);
    __syncthreads();   // all warps done reading before smem reuse

    // phase 2: h @ Wrk_zr (accumulate)
    load_tiles(smem, sb, tid, A2, row0, M,
               BtHi + (size_t)(256 + col0) * 128, BtLo + (size_t)(256 + col0) * 128);
    mainloop(sb, cx, acc);

    epilogue(cx, acc, bias, C, row0, col0, M, 256);
}

// ---------------- FFMA SGEMM (small readout GEMMs) ----------------
#define APAD 4
template<bool HAS_BIAS, bool ACT_SELU>
__global__ void __launch_bounds__(256) sgemm_kernel(
    const float* __restrict__ A, const float* __restrict__ B,
    const float* __restrict__ bias, float* __restrict__ C,
    int M, int N, int K)
{
    __shared__ float As[16][128 + APAD];
    __shared__ float Bs[16][128];

    const int row0 = blockIdx.x * 128;
    const int col0 = blockIdx.y * 128;
    const int tid = threadIdx.x;
    const int tm = tid >> 4;
    const int tn = tid & 15;

    float acc[8][8];
    #pragma unroll
    for (int i = 0; i < 8; i++)
        #pragma unroll
        for (int j = 0; j < 8; j++) acc[i][j] = 0.f;

    for (int k0 = 0; k0 < K; k0 += 16) {
        #pragma unroll
        for (int it = 0; it < 2; it++) {
            int fi = tid + it * 256;
            int r = fi >> 2;
            int kq = fi & 3;
            int grow = row0 + r;
            float4 v = make_float4(0.f, 0.f, 0.f, 0.f);
            if (grow < M)
                v = *(const float4*)(A + (size_t)grow * K + k0 + kq * 4);
            As[kq * 4 + 0][r] = v.x;
            As[kq * 4 + 1][r] = v.y;
            As[kq * 4 + 2][r] = v.z;
            As[kq * 4 + 3][r] = v.w;
        }
        #pragma unroll
        for (int it = 0; it < 2; it++) {
            int fi = tid + it * 256;
            int kr = fi >> 5;
            int cq = fi & 31;
            float4 v = *(const float4*)(B + (size_t)(k0 + kr) * N + col0 + cq * 4);
            *(float4*)(&Bs[kr][cq * 4]) = v;
        }
        __syncthreads();
        #pragma unroll
        for (int k = 0; k < 16; k++) {
            float a[8], b[8];
            *(float4*)(a)     = *(const float4*)(&As[k][tm * 8]);
            *(float4*)(a + 4) = *(const float4*)(&As[k][tm * 8 + 4]);
            *(float4*)(b)     = *(const float4*)(&Bs[k][tn * 8]);
            *(float4*)(b + 4) = *(const float4*)(&Bs[k][tn * 8 + 4]);
            #pragma unroll
            for (int i = 0; i < 8; i++)
                #pragma unroll
                for (int j = 0; j < 8; j++)
                    acc[i][j] = fmaf(a[i], b[j], acc[i][j]);
        }
        __syncthreads();
    }

    float bcol[8];
    if (HAS_BIAS) {
        #pragma unroll
        for (int j = 0; j < 8; j++) bcol[j] = bias[col0 + tn * 8 + j];
    }
    #pragma unroll
    for (int i = 0; i < 8; i++) {
        int r = row0 + tm * 8 + i;
        if (r >= M) continue;
        #pragma unroll
        for (int j = 0; j < 8; j += 4) {
            float4 v;
            float t0 = acc[i][j + 0], t1 = acc[i][j + 1], t2 = acc[i][j + 2], t3 = acc[i][j + 3];
            if (HAS_BIAS) { t0 += bcol[j]; t1 += bcol[j + 1]; t2 += bcol[j + 2]; t3 += bcol[j + 3]; }
            if (ACT_SELU) { t0 = selu_f(t0); t1 = selu_f(t1); t2 = selu_f(t2); t3 = selu_f(t3); }
            v.x = t0; v.y = t1; v.z = t2; v.w = t3;
            *(float4*)(C + (size_t)r * N + col0 + tn * 8 + j) = v;
        }
    }
}

// ---------------- GRU gates: z,r from S sums; hh from X1h/X2h ----------------
__global__ void gates_kernel(const float* __restrict__ S, const float* __restrict__ X1h,
                             const float* __restrict__ X2h, float* __restrict__ h, int E)
{
    int i = blockIdx.x * blockDim.x + threadIdx.x;
    if (i >= E * 32) return;
    int e = i >> 5;
    int q = i & 31;
    size_t b256i = (size_t)e * 256 + q * 4;
    size_t b128 = (size_t)e * 128 + q * 4;
    float4 sz  = *(const float4*)(S + b256i);
    float4 sr  = *(const float4*)(S + b256i + 128);
    float4 x1h = *(const float4*)(X1h + b128);
    float4 x2h = *(const float4*)(X2h + b128);
    float4 hv  = *(const float4*)(h + b128);
    float4 o;
    { float z = sigmoid_f(sz.x); float r = sigmoid_f(sr.x);
      float hh = tanhf(x1h.x + r * x2h.x); o.x = z * hv.x + (1.f - z) * hh; }
    { float z = sigmoid_f(sz.y); float r = sigmoid_f(sr.y);
      float hh = tanhf(x1h.y + r * x2h.y); o.y = z * hv.y + (1.f - z) * hh; }
    { float z = sigmoid_f(sz.z); float r = sigmoid_f(sr.z);
      float hh = tanhf(x1h.z + r * x2h.z); o.z = z * hv.z + (1.f - z) * hh; }
    { float z = sigmoid_f(sz.w); float r = sigmoid_f(sr.w);
      float hh = tanhf(x1h.w + r * x2h.w); o.w = z * hv.w + (1.f - z) * hh; }
    *(float4*)(h + b128) = o;
}

// ---------------- Graph pooling ----------------
__global__ void pool_kernel(const float* __restrict__ h, const int* __restrict__ gids,
                            float* __restrict__ pool, int E)
{
    int i = blockIdx.x * blockDim.x + threadIdx.x;
    if (i >= E * 32) return;
    int e = i >> 5;
    int q = i & 31;
    int g = gids[e];
    float4 v = *(const float4*)(h + (size_t)e * 128 + q * 4);
    float* dst = pool + (size_t)g * 128 + q * 4;
    asm volatile("red.global.add.v4.f32 [%0], {%1,%2,%3,%4};"
                 :: "l"(dst), "f"(v.x), "f"(v.y), "f"(v.z), "f"(v.w) : "memory");
}

// ---------------- Final readout ----------------
__global__ void final_kernel(const float* __restrict__ h2, const float* __restrict__ W3,
                             const float* __restrict__ b3, float* __restrict__ out, int G)
{
    int w = (blockIdx.x * blockDim.x + threadIdx.x) >> 5;
    int lane = threadIdx.x & 31;
    if (w >= G) return;
    float s = 0.f;
    #pragma unroll
    for (int k = 0; k < 8; k++) {
        int j = k * 32 + lane;
        s = fmaf(h2[(size_t)w * 256 + j], W3[j], s);
    }
    #pragma unroll
    for (int off = 16; off > 0; off >>= 1)
        s += __shfl_xor_sync(0xffffffffu, s, off);
    if (lane == 0) out[w] = s + b3[0];
}

// ---------------- Host orchestration ----------------
extern "C" void kernel_launch(void* const* d_in, const int* in_sizes, int n_in,
                              void* d_out, int out_size)
{
    int o = (n_in >= 16) ? 0 : -1;

    const float* link_state = (const float*)d_in[0];
    const int*   gids       = (const int*)d_in[1];
    const int*   first      = (const int*)d_in[2];
    const int*   second     = (const int*)d_in[3];
    const float* W_msg      = (const float*)d_in[5 + o];
    const float* b_msg      = (const float*)d_in[6 + o];
    const float* gru_k      = (const float*)d_in[7 + o];
    const float* gru_rk     = (const float*)d_in[8 + o];
    const float* gru_b      = (const float*)d_in[9 + o];
    const float* W1         = (const float*)d_in[10 + o];
    const float* b1         = (const float*)d_in[11 + o];
    const float* W2         = (const float*)d_in[12 + o];
    const float* b2         = (const float*)d_in[13 + o];
    const float* W3         = (const float*)d_in[14 + o];
    const float* b3         = (const float*)d_in[15 + o];

    const int E = in_sizes[1];
    const int P = in_sizes[2];
    const int G = out_size;

    float *h, *agg, *UV, *S, *X1h, *X2h, *pool, *r1, *r2, *b256, *bzr;
    __half *WtHi, *WtLo;
    int *off, *cur, *pfirst, *blk;
    cudaGetSymbolAddress((void**)&h,    d_h);
    cudaGetSymbolAddress((void**)&agg,  d_agg);
    cudaGetSymbolAddress((void**)&UV,   d_UV);
    cudaGetSymbolAddress((void**)&S,    d_S);
    cudaGetSymbolAddress((void**)&X1h,  d_X1h);
    cudaGetSymbolAddress((void**)&X2h,  d_X2h);
    cudaGetSymbolAddress((void**)&pool, d_pool);
    cudaGetSymbolAddress((void**)&r1,   d_r1);
    cudaGetSymbolAddress((void**)&r2,   d_r2);
    cudaGetSymbolAddress((void**)&b256, d_b256);
    cudaGetSymbolAddress((void**)&bzr,  d_bzr);
    cudaGetSymbolAddress((void**)&WtHi, d_WtHi);
    cudaGetSymbolAddress((void**)&WtLo, d_WtLo);
    cudaGetSymbolAddress((void**)&off,    d_off);
    cudaGetSymbolAddress((void**)&cur,    d_cur);
    cudaGetSymbolAddress((void**)&pfirst, d_pfirst);
    cudaGetSymbolAddress((void**)&blk,    d_blk);

    cudaFuncSetAttribute(mma_gemm,    cudaFuncAttributeMaxDynamicSharedMemorySize, SMEM_SZ);
    cudaFuncSetAttribute(mma_gemm_zr, cudaFuncAttributeMaxDynamicSharedMemorySize, SMEM_SZ);

    // side stream + events (created once, pre-capture)
    static cudaStream_t s1 = nullptr;
    static cudaEvent_t ev_h = nullptr, ev_x2h = nullptr;
    if (s1 == nullptr) {
        cudaStreamCreateWithFlags(&s1, cudaStreamNonBlocking);
        cudaEventCreateWithFlags(&ev_h,   cudaEventDisableTiming);
        cudaEventCreateWithFlags(&ev_x2h, cudaEventDisableTiming);
    }

    const int mb = (E + 95) / 96;
    const int nscan = E + 1;
    const int nblks = (nscan + 1023) / 1024;

    // ---- one-time prep ----
    prep_weights<<<(1024 * 128 + 255) / 256, 256>>>(gru_k, gru_rk, W_msg, b_msg, gru_b,
                                                    WtHi, WtLo, b256, bzr);
    cudaMemcpyAsync(h, link_state, (size_t)E * DIM * sizeof(float), cudaMemcpyDeviceToDevice);
    cudaMemsetAsync(off, 0, (size_t)nscan * sizeof(int));
    k_hist<<<(P + 255) / 256, 256>>>(second, off, P);
    k_scan1<<<nblks, 1024>>>(off, blk, nscan);
    k_scan2<<<1, 1024>>>(blk, nblks);
    k_scan3<<<nblks, 1024>>>(off, blk, cur, nscan, E);
    k_scatter<<<(P + 255) / 256, 256>>>(first, second, cur, pfirst, P);

    for (int t = 0; t < TSTEPS; t++) {
        // h ready on stream 0
        cudaEventRecord(ev_h, 0);
        // fork: X2h = h @ Wrk_h + b1h (rows 640..767)
        cudaStreamWaitEvent(s1, ev_h, 0);
        mma_gemm<<<dim3(mb, 1), 256, SMEM_SZ, s1>>>(h, WtHi, WtLo, gru_b + 640, X2h, E, 128, 640);
        cudaEventRecord(ev_x2h, s1);
        // main: UV (rows 768..1023, V gets +b_msg) -> seg -> ZR sums -> X1h
        mma_gemm<<<dim3(mb, 2), 256, SMEM_SZ>>>(h, WtHi, WtLo, b256, UV, E, 256, 768);
        seg_msg<<<(E + 7) / 8, 256>>>(UV, off, pfirst, agg, E);
        mma_gemm_zr<<<dim3(mb, 2), 256, SMEM_SZ>>>(agg, h, WtHi, WtLo, bzr, S, E);
        mma_gemm<<<dim3(mb, 1), 256, SMEM_SZ>>>(agg, WtHi, WtLo, gru_b + 256, X1h, E, 128, 512);
        // join
        cudaStreamWaitEvent(0, ev_x2h, 0);
        gates_kernel<<<(E * 32 + 255) / 256, 256>>>(S, X1h, X2h, h, E);
    }

    cudaMemsetAsync(pool, 0, (size_t)G * DIM * sizeof(float));
    pool_kernel<<<(E * 32 + 255) / 256, 256>>>(h, gids, pool, E);
    const int gblocks = (G + 127) / 128;
    sgemm_kernel<true, true><<<dim3(gblocks, 2), 256>>>(pool, W1, b1, r1, G, 256, 128);
    sgemm_kernel<true, true><<<dim3(gblocks, 2), 256>>>(r1, W2, b2, r2, G, 256, 256);
    final_kernel<<<(G * 32 + 255) / 256, 256>>>(r2, W3, b3, (float*)d_out, G);
}

// round 17
// speedup vs baseline: 1.0079x; 1.0079x over previous
#include <cuda_runtime.h>
#include <cuda_fp16.h>
#include <math.h>
#include <stdint.h>

// ---------------- Problem constants ----------------
#define DIM   128
#define E_MAX 100000
#define P_MAX 800000
#define G_MAX 1000
#define TSTEPS 8

// ---------------- Device scratch (no allocations allowed) ----------------
__device__ float d_h  [E_MAX * DIM];
__device__ float d_agg[E_MAX * DIM];
__device__ float d_U  [E_MAX * DIM];   // U = h @ W_top  (random-gather target, dense)
__device__ float d_Vb [E_MAX * DIM];   // V + b_msg      (streamed)
__device__ float d_X1 [E_MAX * 384];
__device__ float d_X2 [E_MAX * 384];
__device__ float d_pool[G_MAX * DIM];
__device__ float d_r1 [G_MAX * 256];
__device__ float d_r2 [G_MAX * 256];
__device__ float d_b256[256];          // [0..127]=0, [128..255]=b_msg
// split+transposed weights: rows 0..383 = gru_kernel^T, 384..767 = gru_rec^T, 768..1023 = Wuv^T
__device__ __half d_WtHi[1024 * 128];
__device__ __half d_WtLo[1024 * 128];
// CSR grouping of pairs by `second`
__device__ int d_off   [E_MAX + 1];
__device__ int d_cur   [E_MAX];
__device__ int d_pfirst[P_MAX];
__device__ int d_blk   [256];

// ---------------- math helpers ----------------
__device__ __forceinline__ float selu_f(float x) {
    const float sc = 1.0507009873554805f;
    const float al = 1.6732632423543772f;
    return x > 0.f ? sc * x : sc * al * (expf(x) - 1.f);
}
__device__ __forceinline__ float sigmoid_f(float x) { return 1.f / (1.f + expf(-x)); }

__device__ __forceinline__ uint32_t smem_u32(const void* p) {
    uint32_t a;
    asm("{ .reg .u64 t; cvta.to.shared.u64 t, %1; cvt.u32.u64 %0, t; }" : "=r"(a) : "l"(p));
    return a;
}

#define CP_ASYNC16(dst, src) \
    asm volatile("cp.async.cg.shared.global [%0], [%1], 16;" :: "r"(dst), "l"(src))
#define CP_COMMIT() asm volatile("cp.async.commit_group;" ::: "memory")
#define CP_WAIT0()  asm volatile("cp.async.wait_group 0;" ::: "memory")

// swizzled byte offset of 16B chunk c8 (0..15) in row r (256B rows)
__device__ __forceinline__ uint32_t sw_off(int r, int c8) {
    return ((uint32_t)r << 8) + (uint32_t)((c8 ^ (r & 7)) << 4);
}

__device__ __forceinline__ void ldsm_x4(uint32_t addr, uint32_t* r) {
    asm volatile("ldmatrix.sync.aligned.m8n8.x4.shared.b16 {%0,%1,%2,%3}, [%4];"
                 : "=r"(r[0]), "=r"(r[1]), "=r"(r[2]), "=r"(r[3]) : "r"(addr));
}

__device__ __forceinline__ void mma16816(float* c, const uint32_t* a, uint32_t b0, uint32_t b1) {
    asm volatile(
        "mma.sync.aligned.m16n8k16.row.col.f32.f16.f16.f32 "
        "{%0,%1,%2,%3}, {%4,%5,%6,%7}, {%8,%9}, {%0,%1,%2,%3};"
        : "+f"(c[0]), "+f"(c[1]), "+f"(c[2]), "+f"(c[3])
        : "r"(a[0]), "r"(a[1]), "r"(a[2]), "r"(a[3]), "r"(b0), "r"(b1));
}

// split fp32 float4 into fp16 hi/lo pairs packed as uint2
__device__ __forceinline__ void split4(float4 v, uint2& hu, uint2& lu) {
    __half2 h01 = __floats2half2_rn(v.x, v.y);
    __half2 h23 = __floats2half2_rn(v.z, v.w);
    float lx = v.x - __half2float(__low2half(h01));
    float ly = v.y - __half2float(__high2half(h01));
    float lz = v.z - __half2float(__low2half(h23));
    float lw = v.w - __half2float(__high2half(h23));
    __half2 l01 = __floats2half2_rn(lx, ly);
    __half2 l23 = __floats2half2_rn(lz, lw);
    hu.x = *(uint32_t*)&h01; hu.y = *(uint32_t*)&h23;
    lu.x = *(uint32_t*)&l01; lu.y = *(uint32_t*)&l23;
}

// ---------------- Weight prep ----------------
__global__ void prep_weights(const float* __restrict__ gru_k, const float* __restrict__ gru_rk,
                             const float* __restrict__ W_msg, const float* __restrict__ b_msg,
                             __half* __restrict__ WtHi, __half* __restrict__ WtLo,
                             float* __restrict__ b256)
{
    int i = blockIdx.x * blockDim.x + threadIdx.x;
    if (i >= 1024 * 128) return;
    if (i < 256) b256[i] = (i < 128) ? 0.f : b_msg[i - 128];
    int n = i >> 7;
    int k = i & 127;
    float v;
    if (n < 384) {
        v = gru_k[k * 384 + n];
    } else if (n < 768) {
        v = gru_rk[k * 384 + (n - 384)];
    } else {
        int j = n - 768;
        v = (j < 128) ? W_msg[k * 128 + j] : W_msg[(128 + k) * 128 + (j - 128)];
    }
    __half hi = __float2half_rn(v);
    float lo = v - __half2float(hi);
    WtHi[i] = hi;
    WtLo[i] = __float2half_rn(lo);
}

// ================= CSR build: group pairs by `second` =================
__global__ void k_hist(const int* __restrict__ second, int* __restrict__ cnt, int P) {
    int p = blockIdx.x * blockDim.x + threadIdx.x;
    if (p < P) atomicAdd(&cnt[second[p] + 1], 1);
}

__global__ void k_scan1(int* __restrict__ data, int* __restrict__ blk, int n) {
    __shared__ int sh[1024];
    int tid = threadIdx.x;
    int i = blockIdx.x * 1024 + tid;
    int v = (i < n) ? data[i] : 0;
    sh[tid] = v;
    __syncthreads();
    #pragma unroll
    for (int off = 1; off < 1024; off <<= 1) {
        int t = (tid >= off) ? sh[tid - off] : 0;
        __syncthreads();
        sh[tid] += t;
        __syncthreads();
    }
    if (i < n) data[i] = sh[tid];
    if (tid == 1023) blk[blockIdx.x] = sh[1023];
}

__global__ void k_scan2(int* __restrict__ blk, int nb) {
    __shared__ int sh[1024];
    int tid = threadIdx.x;
    int v = (tid < nb) ? blk[tid] : 0;
    sh[tid] = v;
    __syncthreads();
    #pragma unroll
    for (int off = 1; off < 1024; off <<= 1) {
        int t = (tid >= off) ? sh[tid - off] : 0;
        __syncthreads();
        sh[tid] += t;
        __syncthreads();
    }
    if (tid < nb) blk[tid] = sh[tid] - v;   // exclusive
}

__global__ void k_scan3(int* __restrict__ data, const int* __restrict__ blk,
                        int* __restrict__ cur, int n, int E) {
    int i = blockIdx.x * 1024 + threadIdx.x;
    if (i >= n) return;
    int v = data[i] + blk[blockIdx.x];
    data[i] = v;
    if (i < E) cur[i] = v;
}

__global__ void k_scatter(const int* __restrict__ first, const int* __restrict__ second,
                          int* __restrict__ cur, int* __restrict__ pfirst, int P) {
    int p = blockIdx.x * blockDim.x + threadIdx.x;
    if (p >= P) return;
    int s = second[p];
    int idx = atomicAdd(&cur[s], 1);
    pfirst[idx] = first[p];
}

// ================= Segment message sum over s in [sBeg, sEnd) =================
__global__ void seg_msg(const float* __restrict__ U, const float* __restrict__ Vb,
                        const int* __restrict__ off, const int* __restrict__ pfirst,
                        float* __restrict__ agg, int sBeg, int sEnd)
{
    int s = sBeg + blockIdx.x * 8 + (threadIdx.x >> 5);
    if (s >= sEnd) return;
    int lane = threadIdx.x & 31;
    int beg = off[s], end = off[s + 1];
    float4 vb = *(const float4*)(Vb + (size_t)s * 128 + lane * 4);
    float4 acc = make_float4(0.f, 0.f, 0.f, 0.f);
    int i = beg;
    for (; i + 4 <= end; i += 4) {
        int f0 = pfirst[i];
        int f1 = pfirst[i + 1];
        int f2 = pfirst[i + 2];
        int f3 = pfirst[i + 3];
        float4 u0 = *(const float4*)(U + (size_t)f0 * 128 + lane * 4);
        float4 u1 = *(const float4*)(U + (size_t)f1 * 128 + lane * 4);
        float4 u2 = *(const float4*)(U + (size_t)f2 * 128 + lane * 4);
        float4 u3 = *(const float4*)(U + (size_t)f3 * 128 + lane * 4);
        acc.x += selu_f(u0.x + vb.x) + selu_f(u1.x + vb.x) + selu_f(u2.x + vb.x) + selu_f(u3.x + vb.x);
        acc.y += selu_f(u0.y + vb.y) + selu_f(u1.y + vb.y) + selu_f(u2.y + vb.y) + selu_f(u3.y + vb.y);
        acc.z += selu_f(u0.z + vb.z) + selu_f(u1.z + vb.z) + selu_f(u2.z + vb.z) + selu_f(u3.z + vb.z);
        acc.w += selu_f(u0.w + vb.w) + selu_f(u1.w + vb.w) + selu_f(u2.w + vb.w) + selu_f(u3.w + vb.w);
    }
    for (; i < end; i++) {
        int f = pfirst[i];
        float4 u = *(const float4*)(U + (size_t)f * 128 + lane * 4);
        acc.x += selu_f(u.x + vb.x);
        acc.y += selu_f(u.y + vb.y);
        acc.z += selu_f(u.z + vb.z);
        acc.w += selu_f(u.w + vb.w);
    }
    *(float4*)(agg + (size_t)s * 128 + lane * 4) = acc;
}

// ================= Tensor-core GEMM: 96x128 tile, 2 CTAs/SM, fused loads =================
// SPLIT_UV: blockIdx.y==0 writes C (U, stride 128), ==1 writes C2 (Vb, stride 128), bias from b256.
#define SA_HI 0
#define SA_LO 24576
#define SB_HI 49152
#define SB_LO 81920
#define SMEM_SZ 114688

template<bool HAS_BIAS, bool SPLIT_UV>
__global__ void __launch_bounds__(256, 2) mma_gemm(
    const float* __restrict__ A, const __half* __restrict__ BtHi,
    const __half* __restrict__ BtLo, const float* __restrict__ bias,
    float* __restrict__ C, float* __restrict__ C2, int M, int Ntot)
{
    extern __shared__ __align__(128) char smem[];
    const uint32_t sb = smem_u32(smem);
    const int tid = threadIdx.x;
    const int row0 = blockIdx.x * 96;
    const int col0 = blockIdx.y * 128;

    // ---- B tiles via cp.async ----
    #pragma unroll
    for (int it = 0; it < 16; it++) {
        int idx = it * 256 + tid;
        int m = idx >> 11;
        int ci = idx & 2047;
        int n = ci >> 4;
        int c8 = ci & 15;
        const __half* src = (m ? BtLo : BtHi) + (size_t)(col0 + n) * 128 + c8 * 8;
        uint32_t dst = sb + (m ? SB_LO : SB_HI) + sw_off(n, c8);
        CP_ASYNC16(dst, src);
    }
    CP_COMMIT();

    // ---- A tile: 96 x 128 fp32 -> fp16 hi/lo swizzled ----
    #pragma unroll
    for (int it = 0; it < 12; it++) {
        int idx = it * 256 + tid;
        int r = idx >> 5;
        int c4 = idx & 31;
        int grow = row0 + r;
        float4 v = make_float4(0.f, 0.f, 0.f, 0.f);
        if (grow < M) v = *(const float4*)(A + (size_t)grow * 128 + c4 * 4);
        uint2 hu, lu;
        split4(v, hu, lu);
        uint32_t off = ((uint32_t)r << 8) + (uint32_t)((((c4 >> 1) ^ (r & 7)) << 4) | ((c4 & 1) << 3));
        *(uint2*)(smem + SA_HI + off) = hu;
        *(uint2*)(smem + SA_LO + off) = lu;
    }
    CP_WAIT0();
    __syncthreads();

    const int wid = tid >> 5;
    const int lane = tid & 31;
    const int wr = wid >> 2;
    const int wc = wid & 3;
    const int g = lane >> 3;
    const int l8 = lane & 7;

    float acc[3][4][4];
    #pragma unroll
    for (int i = 0; i < 3; i++)
        #pragma unroll
        for (int j = 0; j < 4; j++)
            #pragma unroll
            for (int q = 0; q < 4; q++) acc[i][j][q] = 0.f;

    uint32_t aBase[3], aX[3];
    #pragma unroll
    for (int mt = 0; mt < 3; mt++) {
        int r = wr * 48 + mt * 16 + (g & 1) * 8 + l8;
        aBase[mt] = (uint32_t)r << 8;
        aX[mt] = (uint32_t)(r & 7);
    }
    uint32_t bBase[2], bX[2];
    #pragma unroll
    for (int nt = 0; nt < 2; nt++) {
        int r = wc * 32 + nt * 16 + (g >> 1) * 8 + l8;
        bBase[nt] = (uint32_t)r << 8;
        bX[nt] = (uint32_t)(r & 7);
    }
    const uint32_t aC8 = (uint32_t)(g >> 1);
    const uint32_t bC8 = (uint32_t)(g & 1);

    #pragma unroll
    for (int ks = 0; ks < 8; ks++) {
        uint32_t aHi[3][4], aLo[3][4];
        #pragma unroll
        for (int mt = 0; mt < 3; mt++) {
            uint32_t aoff = aBase[mt] + ((((uint32_t)(2 * ks) + aC8) ^ aX[mt]) << 4);
            ldsm_x4(sb + SA_HI + aoff, aHi[mt]);
            ldsm_x4(sb + SA_LO + aoff, aLo[mt]);
        }
        uint32_t bHi[2][4], bLo[2][4];
        #pragma unroll
        for (int nt = 0; nt < 2; nt++) {
            uint32_t boff = bBase[nt] + ((((uint32_t)(2 * ks) + bC8) ^ bX[nt]) << 4);
            ldsm_x4(sb + SB_HI + boff, bHi[nt]);
            ldsm_x4(sb + SB_LO + boff, bLo[nt]);
        }
        #pragma unroll
        for (int mt = 0; mt < 3; mt++)
            #pragma unroll
            for (int j = 0; j < 4; j++) {
                uint32_t b0 = (j & 1) ? bHi[j >> 1][2] : bHi[j >> 1][0];
                uint32_t b1 = (j & 1) ? bHi[j >> 1][3] : bHi[j >> 1][1];
                mma16816(acc[mt][j], aHi[mt], b0, b1);
            }
        #pragma unroll
        for (int mt = 0; mt < 3; mt++)
            #pragma unroll
            for (int j = 0; j < 4; j++) {
                uint32_t b0 = (j & 1) ? bLo[j >> 1][2] : bLo[j >> 1][0];
                uint32_t b1 = (j & 1) ? bLo[j >> 1][3] : bLo[j >> 1][1];
                mma16816(acc[mt][j], aHi[mt], b0, b1);
            }
        #pragma unroll
        for (int mt = 0; mt < 3; mt++)
            #pragma unroll
            for (int j = 0; j < 4; j++) {
                uint32_t b0 = (j & 1) ? bHi[j >> 1][2] : bHi[j >> 1][0];
                uint32_t b1 = (j & 1) ? bHi[j >> 1][3] : bHi[j >> 1][1];
                mma16816(acc[mt][j], aLo[mt], b0, b1);
            }
    }

    // ---- epilogue ----
    float* outC = C;
    int cstride = Ntot;
    int cbase = col0;
    if (SPLIT_UV) {
        outC = (blockIdx.y == 0) ? C : C2;
        cstride = 128;
        cbase = 0;
    }
    #pragma unroll
    for (int mt = 0; mt < 3; mt++) {
        int r0a = row0 + wr * 48 + mt * 16 + (lane >> 2);
        #pragma unroll
        for (int j = 0; j < 4; j++) {
            int cl = wc * 32 + j * 8 + (lane & 3) * 2;
            int c = col0 + cl;           // global column (for bias)
            float b0 = 0.f, b1 = 0.f;
            if (HAS_BIAS) { b0 = bias[c]; b1 = bias[c + 1]; }
            int cw = cbase + cl;         // write column
            if (r0a < M) {
                float2 v; v.x = acc[mt][j][0] + b0; v.y = acc[mt][j][1] + b1;
                *(float2*)(outC + (size_t)r0a * cstride + cw) = v;
            }
            if (r0a + 8 < M) {
                float2 v; v.x = acc[mt][j][2] + b0; v.y = acc[mt][j][3] + b1;
                *(float2*)(outC + (size_t)(r0a + 8) * cstride + cw) = v;
            }
        }
    }
}

// ---------------- FFMA SGEMM (small readout GEMMs) ----------------
#define APAD 4
template<bool HAS_BIAS, bool ACT_SELU>
__global__ void __launch_bounds__(256) sgemm_kernel(
    const float* __restrict__ A, const float* __restrict__ B,
    const float* __restrict__ bias, float* __restrict__ C,
    int M, int N, int K)
{
    __shared__ float As[16][128 + APAD];
    __shared__ float Bs[16][128];

    const int row0 = blockIdx.x * 128;
    const int col0 = blockIdx.y * 128;
    const int tid = threadIdx.x;
    const int tm = tid >> 4;
    const int tn = tid & 15;

    float acc[8][8];
    #pragma unroll
    for (int i = 0; i < 8; i++)
        #pragma unroll
        for (int j = 0; j < 8; j++) acc[i][j] = 0.f;

    for (int k0 = 0; k0 < K; k0 += 16) {
        #pragma unroll
        for (int it = 0; it < 2; it++) {
            int fi = tid + it * 256;
            int r = fi >> 2;
            int kq = fi & 3;
            int grow = row0 + r;
            float4 v = make_float4(0.f, 0.f, 0.f, 0.f);
            if (grow < M)
                v = *(const float4*)(A + (size_t)grow * K + k0 + kq * 4);
            As[kq * 4 + 0][r] = v.x;
            As[kq * 4 + 1][r] = v.y;
            As[kq * 4 + 2][r] = v.z;
            As[kq * 4 + 3][r] = v.w;
        }
        #pragma unroll
        for (int it = 0; it < 2; it++) {
            int fi = tid + it * 256;
            int kr = fi >> 5;
            int cq = fi & 31;
            float4 v = *(const float4*)(B + (size_t)(k0 + kr) * N + col0 + cq * 4);
            *(float4*)(&Bs[kr][cq * 4]) = v;
        }
        __syncthreads();
        #pragma unroll
        for (int k = 0; k < 16; k++) {
            float a[8], b[8];
            *(float4*)(a)     = *(const float4*)(&As[k][tm * 8]);
            *(float4*)(a + 4) = *(const float4*)(&As[k][tm * 8 + 4]);
            *(float4*)(b)     = *(const float4*)(&Bs[k][tn * 8]);
            *(float4*)(b + 4) = *(const float4*)(&Bs[k][tn * 8 + 4]);
            #pragma unroll
            for (int i = 0; i < 8; i++)
                #pragma unroll
                for (int j = 0; j < 8; j++)
                    acc[i][j] = fmaf(a[i], b[j], acc[i][j]);
        }
        __syncthreads();
    }

    float bcol[8];
    if (HAS_BIAS) {
        #pragma unroll
        for (int j = 0; j < 8; j++) bcol[j] = bias[col0 + tn * 8 + j];
    }
    #pragma unroll
    for (int i = 0; i < 8; i++) {
        int r = row0 + tm * 8 + i;
        if (r >= M) continue;
        #pragma unroll
        for (int j = 0; j < 8; j += 4) {
            float4 v;
            float t0 = acc[i][j + 0], t1 = acc[i][j + 1], t2 = acc[i][j + 2], t3 = acc[i][j + 3];
            if (HAS_BIAS) { t0 += bcol[j]; t1 += bcol[j + 1]; t2 += bcol[j + 2]; t3 += bcol[j + 3]; }
            if (ACT_SELU) { t0 = selu_f(t0); t1 = selu_f(t1); t2 = selu_f(t2); t3 = selu_f(t3); }
            v.x = t0; v.y = t1; v.z = t2; v.w = t3;
            *(float4*)(C + (size_t)r * N + col0 + tn * 8 + j) = v;
        }
    }
}

// ---------------- GRU gates over rows [eBeg, eEnd) ----------------
__global__ void gates_kernel(const float* __restrict__ X1, const float* __restrict__ X2,
                             float* __restrict__ h, int eBeg, int eEnd)
{
    int i = blockIdx.x * blockDim.x + threadIdx.x;
    int e = eBeg + (i >> 5);
    if (e >= eEnd) return;
    int q = i & 31;
    size_t b384 = (size_t)e * 384 + q * 4;
    size_t b128 = (size_t)e * 128 + q * 4;
    float4 x1z = *(const float4*)(X1 + b384);
    float4 x1r = *(const float4*)(X1 + b384 + 128);
    float4 x1h = *(const float4*)(X1 + b384 + 256);
    float4 x2z = *(const float4*)(X2 + b384);
    float4 x2r = *(const float4*)(X2 + b384 + 128);
    float4 x2h = *(const float4*)(X2 + b384 + 256);
    float4 hv  = *(const float4*)(h + b128);
    float4 o;
    { float z = sigmoid_f(x1z.x + x2z.x); float r = sigmoid_f(x1r.x + x2r.x);
      float hh = tanhf(x1h.x + r * x2h.x); o.x = z * hv.x + (1.f - z) * hh; }
    { float z = sigmoid_f(x1z.y + x2z.y); float r = sigmoid_f(x1r.y + x2r.y);
      float hh = tanhf(x1h.y + r * x2h.y); o.y = z * hv.y + (1.f - z) * hh; }
    { float z = sigmoid_f(x1z.z + x2z.z); float r = sigmoid_f(x1r.z + x2r.z);
      float hh = tanhf(x1h.z + r * x2h.z); o.z = z * hv.z + (1.f - z) * hh; }
    { float z = sigmoid_f(x1z.w + x2z.w); float r = sigmoid_f(x1r.w + x2r.w);
      float hh = tanhf(x1h.w + r * x2h.w); o.w = z * hv.w + (1.f - z) * hh; }
    *(float4*)(h + b128) = o;
}

// ---------------- Graph pooling ----------------
__global__ void pool_kernel(const float* __restrict__ h, const int* __restrict__ gids,
                            float* __restrict__ pool, int E)
{
    int i = blockIdx.x * blockDim.x + threadIdx.x;
    if (i >= E * 32) return;
    int e = i >> 5;
    int q = i & 31;
    int g = gids[e];
    float4 v = *(const float4*)(h + (size_t)e * 128 + q * 4);
    float* dst = pool + (size_t)g * 128 + q * 4;
    asm volatile("red.global.add.v4.f32 [%0], {%1,%2,%3,%4};"
                 :: "l"(dst), "f"(v.x), "f"(v.y), "f"(v.z), "f"(v.w) : "memory");
}

// ---------------- Final readout ----------------
__global__ void final_kernel(const float* __restrict__ h2, const float* __restrict__ W3,
                             const float* __restrict__ b3, float* __restrict__ out, int G)
{
    int w = (blockIdx.x * blockDim.x + threadIdx.x) >> 5;
    int lane = threadIdx.x & 31;
    if (w >= G) return;
    float s = 0.f;
    #pragma unroll
    for (int k = 0; k < 8; k++) {
        int j = k * 32 + lane;
        s = fmaf(h2[(size_t)w * 256 + j], W3[j], s);
    }
    #pragma unroll
    for (int off = 16; off > 0; off >>= 1)
        s += __shfl_xor_sync(0xffffffffu, s, off);
    if (lane == 0) out[w] = s + b3[0];
}

// ---------------- Host orchestration ----------------
extern "C" void kernel_launch(void* const* d_in, const int* in_sizes, int n_in,
                              void* d_out, int out_size)
{
    int o = (n_in >= 16) ? 0 : -1;

    const float* link_state = (const float*)d_in[0];
    const int*   gids       = (const int*)d_in[1];
    const int*   first      = (const int*)d_in[2];
    const int*   second     = (const int*)d_in[3];
    const float* W_msg      = (const float*)d_in[5 + o];
    const float* b_msg      = (const float*)d_in[6 + o];
    const float* gru_k      = (const float*)d_in[7 + o];
    const float* gru_rk     = (const float*)d_in[8 + o];
    const float* gru_b      = (const float*)d_in[9 + o];
    const float* W1         = (const float*)d_in[10 + o];
    const float* b1         = (const float*)d_in[11 + o];
    const float* W2         = (const float*)d_in[12 + o];
    const float* b2         = (const float*)d_in[13 + o];
    const float* W3         = (const float*)d_in[14 + o];
    const float* b3         = (const float*)d_in[15 + o];

    const int E = in_sizes[1];
    const int P = in_sizes[2];
    const int G = out_size;

    float *h, *agg, *U, *Vb, *X1, *X2, *pool, *r1, *r2, *b256;
    __half *WtHi, *WtLo;
    int *off, *cur, *pfirst, *blk;
    cudaGetSymbolAddress((void**)&h,    d_h);
    cudaGetSymbolAddress((void**)&agg,  d_agg);
    cudaGetSymbolAddress((void**)&U,    d_U);
    cudaGetSymbolAddress((void**)&Vb,   d_Vb);
    cudaGetSymbolAddress((void**)&X1,   d_X1);
    cudaGetSymbolAddress((void**)&X2,   d_X2);
    cudaGetSymbolAddress((void**)&pool, d_pool);
    cudaGetSymbolAddress((void**)&r1,   d_r1);
    cudaGetSymbolAddress((void**)&r2,   d_r2);
    cudaGetSymbolAddress((void**)&b256, d_b256);
    cudaGetSymbolAddress((void**)&WtHi, d_WtHi);
    cudaGetSymbolAddress((void**)&WtLo, d_WtLo);
    cudaGetSymbolAddress((void**)&off,    d_off);
    cudaGetSymbolAddress((void**)&cur,    d_cur);
    cudaGetSymbolAddress((void**)&pfirst, d_pfirst);
    cudaGetSymbolAddress((void**)&blk,    d_blk);

    cudaFuncSetAttribute((const void*)mma_gemm<true, false>, cudaFuncAttributeMaxDynamicSharedMemorySize, SMEM_SZ);
    cudaFuncSetAttribute((const void*)mma_gemm<true, true>,  cudaFuncAttributeMaxDynamicSharedMemorySize, SMEM_SZ);

    // side stream + events (created once, pre-capture)
    static cudaStream_t s1 = nullptr;
    static cudaEvent_t ev_boot = nullptr, ev_uv = nullptr, ev_x2 = nullptr,
                       ev_gA = nullptr, ev_gB = nullptr;
    if (s1 == nullptr) {
        cudaStreamCreateWithFlags(&s1, cudaStreamNonBlocking);
        cudaEventCreateWithFlags(&ev_boot, cudaEventDisableTiming);
        cudaEventCreateWithFlags(&ev_uv,   cudaEventDisableTiming);
        cudaEventCreateWithFlags(&ev_x2,   cudaEventDisableTiming);
        cudaEventCreateWithFlags(&ev_gA,   cudaEventDisableTiming);
        cudaEventCreateWithFlags(&ev_gB,   cudaEventDisableTiming);
    }

    const __half* WkHi  = WtHi;              const __half* WkLo  = WtLo;
    const __half* WrkHi = WtHi + 384 * 128;  const __half* WrkLo = WtLo + 384 * 128;
    const __half* WuvHi = WtHi + 768 * 128;  const __half* WuvLo = WtLo + 768 * 128;

    const int mb = (E + 95) / 96;
    const int Eh = ((E / 2 + 95) / 96) * 96 < E ? ((E / 2 + 95) / 96) * 96 : E;
    const int mbA = (Eh + 95) / 96;
    const int mbB = (E - Eh + 95) / 96;
    const int nscan = E + 1;
    const int nblks = (nscan + 1023) / 1024;

    // ---- one-time prep (stream 0) ----
    prep_weights<<<(1024 * 128 + 255) / 256, 256>>>(gru_k, gru_rk, W_msg, b_msg, WtHi, WtLo, b256);
    cudaMemcpyAsync(h, link_state, (size_t)E * DIM * sizeof(float), cudaMemcpyDeviceToDevice);
    cudaMemsetAsync(off, 0, (size_t)nscan * sizeof(int));
    k_hist<<<(P + 255) / 256, 256>>>(second, off, P);
    k_scan1<<<nblks, 1024>>>(off, blk, nscan);
    k_scan2<<<1, 1024>>>(blk, nblks);
    k_scan3<<<nblks, 1024>>>(off, blk, cur, nscan, E);
    k_scatter<<<(P + 255) / 256, 256>>>(first, second, cur, pfirst, P);
    cudaEventRecord(ev_boot, 0);

    for (int t = 0; t < TSTEPS; t++) {
        // --- stream 1: X2 = h @ Wrk + b (needs full h) ---
        if (t == 0) cudaStreamWaitEvent(s1, ev_boot, 0);
        else        cudaStreamWaitEvent(s1, ev_gA, 0);
        mma_gemm<true, false><<<dim3(mb, 3), 256, SMEM_SZ, s1>>>(h, WrkHi, WrkLo, gru_b + 384, X2, nullptr, E, 384);
        cudaEventRecord(ev_x2, s1);

        // --- stream 0: UV split -> U / Vb ---
        if (t > 0) cudaStreamWaitEvent(0, ev_gB, 0);
        mma_gemm<true, true><<<dim3(mb, 2), 256, SMEM_SZ>>>(h, WuvHi, WuvLo, b256, U, Vb, E, 256);
        cudaEventRecord(ev_uv, 0);

        // --- seg halves ---
        seg_msg<<<(Eh + 7) / 8, 256>>>(U, Vb, off, pfirst, agg, 0, Eh);
        cudaStreamWaitEvent(s1, ev_uv, 0);
        seg_msg<<<(E - Eh + 7) / 8, 256, 0, s1>>>(U, Vb, off, pfirst, agg, Eh, E);

        // --- X1 halves ---
        mma_gemm<true, false><<<dim3(mbA, 3), 256, SMEM_SZ>>>(agg, WkHi, WkLo, gru_b, X1, nullptr, Eh, 384);
        mma_gemm<true, false><<<dim3(mbB, 3), 256, SMEM_SZ, s1>>>(agg + (size_t)Eh * 128, WkHi, WkLo, gru_b,
                                                                  X1 + (size_t)Eh * 384, nullptr, E - Eh, 384);

        // --- gates halves ---
        cudaStreamWaitEvent(0, ev_x2, 0);
        gates_kernel<<<((Eh) * 32 + 255) / 256, 256>>>(X1, X2, h, 0, Eh);
        cudaEventRecord(ev_gA, 0);
        gates_kernel<<<((E - Eh) * 32 + 255) / 256, 256, 0, s1>>>(X1, X2, h, Eh, E);
        cudaEventRecord(ev_gB, s1);
    }

    // readout (stream 0)
    cudaStreamWaitEvent(0, ev_gB, 0);
    cudaMemsetAsync(pool, 0, (size_t)G * DIM * sizeof(float));
    pool_kernel<<<(E * 32 + 255) / 256, 256>>>(h, gids, pool, E);
    const int gblocks = (G + 127) / 128;
    sgemm_kernel<true, true><<<dim3(gblocks, 2), 256>>>(pool, W1, b1, r1, G, 256, 128);
    sgemm_kernel<true, true><<<dim3(gblocks, 2), 256>>>(r1, W2, b2, r2, G, 256, 256);
    final_kernel<<<(G * 32 + 255) / 256, 256>>>(r2, W3, b3, (float*)d_out, G);
}